// round 2
// baseline (speedup 1.0000x reference)
#include <cuda_runtime.h>
#include <cstdint>

// ---------------------------------------------------------------------------
// Problem constants
// ---------------------------------------------------------------------------
#define NN   2048          // nodes / batch
#define CC   16            // channels of x
#define HH   32
#define WW   32
#define HW   (HH*WW)       // 1024
#define FEAT (CC*HW)       // 16384 floats per node

// Scratch (device globals; no allocation allowed in kernel_launch)
__device__ float g_neigh   [NN * CC * HW];   // 134 MB
__device__ float g_nonneigh[NN * CC * HW];   // 134 MB
__device__ float g_h1      [NN * 32 * HW];   // 268 MB
__device__ float g_h2      [NN * 32 * HW];   // 268 MB
__device__ int   g_edges64;                  // 1 if edges buffer is int64

// ---------------------------------------------------------------------------
// Probe: decide whether the edges buffer is int64 or int32.
// If int32 data is reinterpreted as int64, values are composites of two
// consecutive int32 words -> virtually never in-range. Check a handful.
// ---------------------------------------------------------------------------
__global__ void probe_dtype_kernel(const void* edges, int E) {
    const long long* e64 = (const long long*)edges;
    bool ok = true;
    int n = E < 8 ? E : 8;
    for (int i = 0; i < n; i++) {
        long long a   = e64[3 * i + 0];
        long long rel = e64[3 * i + 1];
        long long b   = e64[3 * i + 2];
        if (a < 0 || a >= NN || b < 0 || b >= NN ||
            !(rel == 1 || rel == -1)) { ok = false; break; }
    }
    g_edges64 = ok ? 1 : 0;
}

// ---------------------------------------------------------------------------
// Zero a float buffer (float4 stores)
// ---------------------------------------------------------------------------
__global__ void zero_kernel(float4* __restrict__ p, int n4) {
    int i = blockIdx.x * blockDim.x + threadIdx.x;
    if (i < n4) p[i] = make_float4(0.f, 0.f, 0.f, 0.f);
}

// ---------------------------------------------------------------------------
// Edge scatter: one block per edge.
//   nodes[b] += x[a]*mask ; nodes[a] += x[b]*mask, mask selects neigh/nonneigh
// ---------------------------------------------------------------------------
__global__ void scatter_kernel(const float* __restrict__ x,
                               const void* __restrict__ edges,
                               float* __restrict__ neigh,
                               float* __restrict__ nonneigh) {
    int e = blockIdx.x;
    long long a, rel, b;
    if (g_edges64) {
        const long long* e64 = (const long long*)edges;
        a   = e64[3 * e + 0];
        rel = e64[3 * e + 1];
        b   = e64[3 * e + 2];
    } else {
        const int* e32 = (const int*)edges;
        a   = e32[3 * e + 0];
        rel = e32[3 * e + 1];
        b   = e32[3 * e + 2];
    }
    // Defensive clamp (keeps a bad probe from crashing; wrong answer instead)
    if (a < 0 || a >= NN || b < 0 || b >= NN) return;

    float* dst = (rel > 0) ? neigh : nonneigh;

    const float4* xa = (const float4*)(x + (size_t)a * FEAT);
    const float4* xb = (const float4*)(x + (size_t)b * FEAT);
    float* da = dst + (size_t)a * FEAT;
    float* db = dst + (size_t)b * FEAT;

    for (int i = threadIdx.x; i < FEAT / 4; i += blockDim.x) {
        float4 va = xa[i];
        atomicAdd(&db[4 * i + 0], va.x);
        atomicAdd(&db[4 * i + 1], va.y);
        atomicAdd(&db[4 * i + 2], va.z);
        atomicAdd(&db[4 * i + 3], va.w);
        float4 vb = xb[i];
        atomicAdd(&da[4 * i + 0], vb.x);
        atomicAdd(&da[4 * i + 1], vb.y);
        atomicAdd(&da[4 * i + 2], vb.z);
        atomicAdd(&da[4 * i + 3], vb.w);
    }
}

// ---------------------------------------------------------------------------
// Direct 3x3 conv, pad=1, NCHW. Input channels processed in chunks of 16.
// Block = 256 threads = 32 (x) * 8 (rows). Grid = (N, 4 row tiles).
// Input may be split across up to 3 source arrays (16 ch per chunk):
//   chunk ch reads: src_ch + n*imgStride + cl*HW
// Weights staged in smem as [cl][co][12] (9 taps padded to 12 for float4).
// ---------------------------------------------------------------------------
template <int CIN, int COUT>
__global__ void __launch_bounds__(256)
conv3x3_kernel(const float* __restrict__ src0,
               const float* __restrict__ src1,
               const float* __restrict__ src2,
               int imgStride,
               const float* __restrict__ w,
               const float* __restrict__ bias,
               float* __restrict__ out) {
    constexpr int NCH = CIN / 16;
    __shared__ float s_in[16 * 10 * 34];       // 21.25 KB
    __shared__ float s_w[16 * COUT * 12];      // <= 24 KB

    const int n   = blockIdx.x;
    const int ty0 = blockIdx.y * 8;
    const int tx  = threadIdx.x & 31;
    const int ty  = threadIdx.x >> 5;

    float acc[COUT];
#pragma unroll
    for (int co = 0; co < COUT; co++) acc[co] = bias[co];

#pragma unroll 1
    for (int ch = 0; ch < NCH; ch++) {
        const float* base =
            ((ch == 0) ? src0 : (ch == 1) ? src1 : src2) + (size_t)n * imgStride;

        // stage input tile: 16 ch x 10 rows x 34 cols (zero-padded halo)
        for (int idx = threadIdx.x; idx < 16 * 10 * 34; idx += 256) {
            int c   = idx / 340;
            int rem = idx - c * 340;
            int r   = rem / 34;
            int col = rem - r * 34;
            int gr = ty0 + r - 1;
            int gc = col - 1;
            float v = 0.f;
            if (gr >= 0 && gr < HH && gc >= 0 && gc < WW)
                v = base[c * HW + gr * WW + gc];
            s_in[idx] = v;
        }
        // stage weights for this ci chunk: s_w[cl][co][tap(0..8)] pad 12
        for (int idx = threadIdx.x; idx < 16 * COUT * 9; idx += 256) {
            int cl  = idx / (COUT * 9);
            int rr  = idx - cl * (COUT * 9);
            int co  = rr / 9;
            int tap = rr - co * 9;
            s_w[(cl * COUT + co) * 12 + tap] =
                w[(size_t)(co * CIN + ch * 16 + cl) * 9 + tap];
        }
        __syncthreads();

#pragma unroll 1
        for (int cl = 0; cl < 16; cl++) {
            float iv[9];
#pragma unroll
            for (int ky = 0; ky < 3; ky++)
#pragma unroll
                for (int kx = 0; kx < 3; kx++)
                    iv[ky * 3 + kx] = s_in[(cl * 10 + ty + ky) * 34 + tx + kx];
#pragma unroll
            for (int co = 0; co < COUT; co++) {
                const float4* wp = (const float4*)&s_w[(cl * COUT + co) * 12];
                float4 w0 = wp[0];
                float4 w1 = wp[1];
                float  w8 = s_w[(cl * COUT + co) * 12 + 8];
                acc[co] += iv[0] * w0.x + iv[1] * w0.y + iv[2] * w0.z +
                           iv[3] * w0.w + iv[4] * w1.x + iv[5] * w1.y +
                           iv[6] * w1.z + iv[7] * w1.w + iv[8] * w8;
            }
        }
        __syncthreads();
    }

    float* o = out + (size_t)n * COUT * HW + (ty0 + ty) * WW + tx;
#pragma unroll
    for (int co = 0; co < COUT; co++) o[co * HW] = acc[co];
}

// ---------------------------------------------------------------------------
// Launch
// ---------------------------------------------------------------------------
extern "C" void kernel_launch(void* const* d_in, const int* in_sizes, int n_in,
                              void* d_out, int out_size) {
    const float* x     = (const float*)d_in[0];
    const void*  edges = (const void*)d_in[1];
    const float* w1    = (const float*)d_in[2];
    const float* b1    = (const float*)d_in[3];
    const float* w2    = (const float*)d_in[4];
    const float* b2    = (const float*)d_in[5];
    const float* w3    = (const float*)d_in[6];
    const float* b3    = (const float*)d_in[7];
    float*       out   = (float*)d_out;

    const int E = in_sizes[1] / 3;

    float *neigh, *nonneigh, *h1, *h2;
    cudaGetSymbolAddress((void**)&neigh,    g_neigh);
    cudaGetSymbolAddress((void**)&nonneigh, g_nonneigh);
    cudaGetSymbolAddress((void**)&h1,       g_h1);
    cudaGetSymbolAddress((void**)&h2,       g_h2);

    probe_dtype_kernel<<<1, 1>>>(edges, E);

    const int n4     = NN * CC * HW / 4;      // 8,388,608 float4 per buffer
    const int zblks  = (n4 + 255) / 256;

    zero_kernel<<<zblks, 256>>>((float4*)neigh, n4);
    zero_kernel<<<zblks, 256>>>((float4*)nonneigh, n4);

    scatter_kernel<<<E, 256>>>(x, edges, neigh, nonneigh);

    dim3 cgrid(NN, 4);
    // conv1: concat(x, neigh, nonneigh) [48ch] -> h1 [32ch]
    conv3x3_kernel<48, 32><<<cgrid, 256>>>(x, neigh, nonneigh, CC * HW,
                                           w1, b1, h1);
    // conv2: h1 [32ch] -> h2 [32ch]
    conv3x3_kernel<32, 32><<<cgrid, 256>>>(h1, h1 + 16 * HW, nullptr, 32 * HW,
                                           w2, b2, h2);
    // conv3: h2 [32ch] -> out [16ch]
    conv3x3_kernel<32, 16><<<cgrid, 256>>>(h2, h2 + 16 * HW, nullptr, 32 * HW,
                                           w3, b3, out);
}

// round 3
// speedup vs baseline: 1.4872x; 1.4872x over previous
#include <cuda_runtime.h>
#include <cstdint>

// ---------------------------------------------------------------------------
// Problem constants
// ---------------------------------------------------------------------------
#define NN    2048         // nodes / batch
#define CC    16           // channels of x
#define HH    32
#define WW    32
#define HW    (HH*WW)      // 1024
#define FEAT  (CC*HW)      // 16384 floats per node
#define EMAX  16384

// Scratch (device globals; no allocation allowed in kernel_launch)
__device__ float g_neigh   [NN * CC * HW];   // 134 MB
__device__ float g_nonneigh[NN * CC * HW];   // 134 MB
__device__ float g_h1      [NN * 32 * HW];   // 268 MB
__device__ float g_h2      [NN * 32 * HW];   // 268 MB
__device__ int   g_edges64;                  // 1 if edges buffer is int64
__device__ int   g_deg[NN];
__device__ int   g_off[NN + 1];
__device__ int   g_cur[NN];
__device__ int   g_adj[2 * EMAX];            // peer | (0x10000 if rel>0)

// ---------------------------------------------------------------------------
// Edge decode (dtype decided at runtime by probe)
// ---------------------------------------------------------------------------
__device__ __forceinline__ void load_edge(const void* edges, int e,
                                          int& a, int& rel, int& b) {
    if (g_edges64) {
        const long long* p = (const long long*)edges;
        a = (int)p[3 * e + 0]; rel = (int)p[3 * e + 1]; b = (int)p[3 * e + 2];
    } else {
        const int* p = (const int*)edges;
        a = p[3 * e + 0]; rel = p[3 * e + 1]; b = p[3 * e + 2];
    }
}

__global__ void probe_dtype_kernel(const void* edges, int E) {
    const long long* e64 = (const long long*)edges;
    bool ok = true;
    int n = E < 8 ? E : 8;
    for (int i = 0; i < n; i++) {
        long long a   = e64[3 * i + 0];
        long long rel = e64[3 * i + 1];
        long long b   = e64[3 * i + 2];
        if (a < 0 || a >= NN || b < 0 || b >= NN ||
            !(rel == 1 || rel == -1)) { ok = false; break; }
    }
    g_edges64 = ok ? 1 : 0;
}

// ---------------------------------------------------------------------------
// CSR build
// ---------------------------------------------------------------------------
__global__ void csr_zero_kernel() {
    int i = blockIdx.x * blockDim.x + threadIdx.x;
    if (i < NN) g_deg[i] = 0;
}

__global__ void csr_count_kernel(const void* edges, int E) {
    int e = blockIdx.x * blockDim.x + threadIdx.x;
    if (e >= E) return;
    int a, rel, b;
    load_edge(edges, e, a, rel, b);
    if (a < 0 || a >= NN || b < 0 || b >= NN) return;
    atomicAdd(&g_deg[a], 1);
    atomicAdd(&g_deg[b], 1);
}

__global__ void __launch_bounds__(1024) csr_scan_kernel() {
    __shared__ int s[NN];
    int t = threadIdx.x;                       // 1024 threads, 2 elems each
    s[t]        = g_deg[t];
    s[t + 1024] = g_deg[t + 1024];
    __syncthreads();
    for (int d = 1; d < NN; d <<= 1) {
        int v0 = (t        >= d) ? s[t        - d] : 0;
        int v1 = (t + 1024 >= d) ? s[t + 1024 - d] : 0;
        __syncthreads();
        s[t]        += v0;
        s[t + 1024] += v1;
        __syncthreads();
    }
    // inclusive -> exclusive offsets
    g_off[t + 1]    = s[t];
    g_off[t + 1025] = s[t + 1024];
    if (t == 0) g_off[0] = 0;
    g_cur[t]        = (t == 0) ? 0 : s[t - 1];
    g_cur[t + 1024] = s[t + 1023];
}

__global__ void csr_fill_kernel(const void* edges, int E) {
    int e = blockIdx.x * blockDim.x + threadIdx.x;
    if (e >= E) return;
    int a, rel, b;
    load_edge(edges, e, a, rel, b);
    if (a < 0 || a >= NN || b < 0 || b >= NN) return;
    int flag = (rel > 0) ? 0x10000 : 0;
    int pa = atomicAdd(&g_cur[a], 1);
    g_adj[pa] = b | flag;                      // node a accumulates x[b]
    int pb = atomicAdd(&g_cur[b], 1);
    g_adj[pb] = a | flag;                      // node b accumulates x[a]
}

// ---------------------------------------------------------------------------
// Gather: block = (node n, feature half h). 256 threads, each owns 8 float4
// of the 8192-float half, accumulates over incident edges in registers.
// Writes both neigh and nonneigh (zeros where no contributions).
// ---------------------------------------------------------------------------
__global__ void __launch_bounds__(256) gather_kernel(
        const float* __restrict__ x,
        float* __restrict__ neigh,
        float* __restrict__ nonneigh) {
    const int n = blockIdx.x;
    const int h = blockIdx.y;                  // 0 or 1
    const int t = threadIdx.x;

    float4 accN[8], accP[8];
#pragma unroll
    for (int j = 0; j < 8; j++) {
        accN[j] = make_float4(0.f, 0.f, 0.f, 0.f);
        accP[j] = make_float4(0.f, 0.f, 0.f, 0.f);
    }

    const int s = g_off[n], e = g_off[n + 1];
    const size_t base4h = (size_t)h * 2048;    // float4 offset of the half
    const float4* xb = (const float4*)x;

    for (int k = s; k < e; k++) {
        int ent = g_adj[k];
        int peer = ent & 0xFFFF;
        const float4* src = xb + (size_t)peer * (FEAT / 4) + base4h;
        if (ent & 0x10000) {
#pragma unroll
            for (int j = 0; j < 8; j++) {
                float4 v = src[t + 256 * j];
                accN[j].x += v.x; accN[j].y += v.y;
                accN[j].z += v.z; accN[j].w += v.w;
            }
        } else {
#pragma unroll
            for (int j = 0; j < 8; j++) {
                float4 v = src[t + 256 * j];
                accP[j].x += v.x; accP[j].y += v.y;
                accP[j].z += v.z; accP[j].w += v.w;
            }
        }
    }

    float4* dn = (float4*)neigh    + (size_t)n * (FEAT / 4) + base4h;
    float4* dp = (float4*)nonneigh + (size_t)n * (FEAT / 4) + base4h;
#pragma unroll
    for (int j = 0; j < 8; j++) {
        dn[t + 256 * j] = accN[j];
        dp[t + 256 * j] = accP[j];
    }
}

// ---------------------------------------------------------------------------
// Direct 3x3 conv, pad=1, NCHW. 2 output pixels (vertically adjacent rows)
// per thread; input channels in chunks of 8.
// Block = 256 threads = 32 (x) * 8 (row-pairs) -> 16 rows per block.
// Grid = (N, 2 row tiles). Sources: up to 3 arrays of 16 channels each;
// chunk ch reads source ch>>1 at channel offset (ch&1)*8.
// ---------------------------------------------------------------------------
template <int CIN, int COUT>
__global__ void __launch_bounds__(256)
conv3x3_kernel(const float* __restrict__ src0,
               const float* __restrict__ src1,
               const float* __restrict__ src2,
               int imgStride,
               const float* __restrict__ w,
               const float* __restrict__ bias,
               float* __restrict__ out) {
    constexpr int NCH = CIN / 8;
    __shared__ float s_in[8 * 18 * 34];        // 19.1 KB
    __shared__ float s_w[8 * COUT * 12];       // <= 12.3 KB

    const int n     = blockIdx.x;
    const int rbase = blockIdx.y * 16;
    const int tx    = threadIdx.x & 31;
    const int ty    = threadIdx.x >> 5;        // 0..7 -> rows 2ty, 2ty+1

    float acc0[COUT], acc1[COUT];
#pragma unroll
    for (int co = 0; co < COUT; co++) { acc0[co] = bias[co]; acc1[co] = bias[co]; }

#pragma unroll 1
    for (int ch = 0; ch < NCH; ch++) {
        const float* srcp = (ch >> 1) == 0 ? src0 : ((ch >> 1) == 1 ? src1 : src2);
        const float* base = srcp + (size_t)n * imgStride + (ch & 1) * 8 * HW;

        // stage input: 8 ch x 18 rows x 34 cols (zero-padded halo)
        for (int idx = threadIdx.x; idx < 8 * 18 * 34; idx += 256) {
            int c   = idx / 612;
            int rem = idx - c * 612;
            int r   = rem / 34;
            int col = rem - r * 34;
            int gr = rbase + r - 1;
            int gc = col - 1;
            float v = 0.f;
            if (gr >= 0 && gr < HH && gc >= 0 && gc < WW)
                v = base[c * HW + gr * WW + gc];
            s_in[idx] = v;
        }
        // stage weights: s_w[cl][co][tap 0..8] padded to 12
        for (int idx = threadIdx.x; idx < 8 * COUT * 9; idx += 256) {
            int cl  = idx / (COUT * 9);
            int rr  = idx - cl * (COUT * 9);
            int co  = rr / 9;
            int tap = rr - co * 9;
            s_w[(cl * COUT + co) * 12 + tap] =
                w[(size_t)(co * CIN + ch * 8 + cl) * 9 + tap];
        }
        __syncthreads();

#pragma unroll 1
        for (int cl = 0; cl < 8; cl++) {
            // 4 rows x 3 cols of input covering both output pixels
            float iv[4][3];
#pragma unroll
            for (int rr = 0; rr < 4; rr++)
#pragma unroll
                for (int cc = 0; cc < 3; cc++)
                    iv[rr][cc] = s_in[(cl * 18 + 2 * ty + rr) * 34 + tx + cc];
#pragma unroll
            for (int co = 0; co < COUT; co++) {
                const float4* wp = (const float4*)&s_w[(cl * COUT + co) * 12];
                float4 w0 = wp[0];
                float4 w1 = wp[1];
                float  w8 = s_w[(cl * COUT + co) * 12 + 8];
                acc0[co] += iv[0][0] * w0.x + iv[0][1] * w0.y + iv[0][2] * w0.z +
                            iv[1][0] * w0.w + iv[1][1] * w1.x + iv[1][2] * w1.y +
                            iv[2][0] * w1.z + iv[2][1] * w1.w + iv[2][2] * w8;
                acc1[co] += iv[1][0] * w0.x + iv[1][1] * w0.y + iv[1][2] * w0.z +
                            iv[2][0] * w0.w + iv[2][1] * w1.x + iv[2][2] * w1.y +
                            iv[3][0] * w1.z + iv[3][1] * w1.w + iv[3][2] * w8;
            }
        }
        __syncthreads();
    }

    const int gr0 = rbase + 2 * ty;
    float* o = out + (size_t)n * COUT * HW + gr0 * WW + tx;
#pragma unroll
    for (int co = 0; co < COUT; co++) {
        o[co * HW]      = acc0[co];
        o[co * HW + WW] = acc1[co];
    }
}

// ---------------------------------------------------------------------------
// Launch
// ---------------------------------------------------------------------------
extern "C" void kernel_launch(void* const* d_in, const int* in_sizes, int n_in,
                              void* d_out, int out_size) {
    const float* x     = (const float*)d_in[0];
    const void*  edges = (const void*)d_in[1];
    const float* w1    = (const float*)d_in[2];
    const float* b1    = (const float*)d_in[3];
    const float* w2    = (const float*)d_in[4];
    const float* b2    = (const float*)d_in[5];
    const float* w3    = (const float*)d_in[6];
    const float* b3    = (const float*)d_in[7];
    float*       out   = (float*)d_out;

    int E = in_sizes[1] / 3;
    if (E > EMAX) E = EMAX;

    float *neigh, *nonneigh, *h1, *h2;
    cudaGetSymbolAddress((void**)&neigh,    g_neigh);
    cudaGetSymbolAddress((void**)&nonneigh, g_nonneigh);
    cudaGetSymbolAddress((void**)&h1,       g_h1);
    cudaGetSymbolAddress((void**)&h2,       g_h2);

    probe_dtype_kernel<<<1, 1>>>(edges, E);

    // CSR build
    csr_zero_kernel<<<(NN + 255) / 256, 256>>>();
    csr_count_kernel<<<(E + 255) / 256, 256>>>(edges, E);
    csr_scan_kernel<<<1, 1024>>>();
    csr_fill_kernel<<<(E + 255) / 256, 256>>>(edges, E);

    // Message passing (gather, no atomics)
    dim3 ggrid(NN, 2);
    gather_kernel<<<ggrid, 256>>>(x, neigh, nonneigh);

    dim3 cgrid(NN, 2);
    // conv1: concat(x, neigh, nonneigh) [48ch] -> h1 [32ch]
    conv3x3_kernel<48, 32><<<cgrid, 256>>>(x, neigh, nonneigh, CC * HW,
                                           w1, b1, h1);
    // conv2: h1 [32ch] -> h2 [32ch]
    conv3x3_kernel<32, 32><<<cgrid, 256>>>(h1, h1 + 16 * HW, nullptr, 32 * HW,
                                           w2, b2, h2);
    // conv3: h2 [32ch] -> out [16ch]
    conv3x3_kernel<32, 16><<<cgrid, 256>>>(h2, h2 + 16 * HW, nullptr, 32 * HW,
                                           w3, b3, out);
}